// round 11
// baseline (speedup 1.0000x reference)
#include <cuda_runtime.h>
#include <cuda_bf16.h>
#include <cstdint>

// Kohonen SOM pairwise L2 distance via bf16 mma.sync.m16n8k16.
//   out[b][n] = sqrt(max(||x_b||^2 + ||w_n||^2 - 2 x_b.w_n, 0))
// x [B=65536,32] f32, w [N=4900,32] f32, out [B,N] f32.
//
// R11 = R10 structure (128x128 CTA tile, 512 threads, 4x4 warp grid, 32x32
// warp tile, permuted fragment columns -> STG.128 epilogue) with OPERANDS IN
// BF16 (norms stay exact fp32): smem tiles, fill stores, and mainloop LDS
// all halve -> ~30% fewer L1 wavefronts (L1 was 86.5%, the binding pipe).
// B rows are stored under a sigma row-permutation chosen so the permuted
// fragment reads become the plain {qr, qr+8} pattern: with b32 pitch 20,
// every mainloop LDS is provably bank-conflict-free.

#define BM 128
#define BN 128
#define KD 32
#define PW 20     // smem pitch in b32 units (20*4=80 B/row); 20r mod 32 distinct mults of 4

// sigma row permutation within each 16-row group of the B tile
__device__ __forceinline__ int sig16(int c) {
    return (((c >> 1) & 1) << 3) + ((c >> 2) << 1) + (c & 1);
}

__device__ __forceinline__ unsigned pack_bf16(float lo, float hi) {
    unsigned r;
    asm("cvt.rn.bf16x2.f32 %0, %1, %2;" : "=r"(r) : "f"(hi), "f"(lo));
    return r;
}

__device__ __forceinline__ float fsqrt_approx(float a) {
    float r;
    asm("sqrt.approx.f32 %0, %1;" : "=f"(r) : "f"(a));
    return r;
}

__device__ __forceinline__ void mma_bf16(float* c, const unsigned* a, const unsigned* b) {
    asm volatile(
        "mma.sync.aligned.m16n8k16.row.col.f32.bf16.bf16.f32 "
        "{%0,%1,%2,%3}, {%4,%5,%6,%7}, {%8,%9}, {%0,%1,%2,%3};"
        : "+f"(c[0]), "+f"(c[1]), "+f"(c[2]), "+f"(c[3])
        : "r"(a[0]), "r"(a[1]), "r"(a[2]), "r"(a[3]),
          "r"(b[0]), "r"(b[1]));
}

__global__ __launch_bounds__(512, 2)
void som_mma_kernel(const float* __restrict__ x,
                    const float* __restrict__ w,
                    float* __restrict__ out,
                    int B, int N) {
    __shared__ unsigned As[BM * PW];   // 10 KB bf16x2(x), pitch 20
    __shared__ unsigned Bs[BN * PW];   // 10 KB bf16x2(w), sigma-permuted rows
    __shared__ float p2[512];          // half-row norm partials
    __shared__ float x2s[BM];
    __shared__ float w2s[BN];

    const int tid    = threadIdx.x;
    const int m_base = blockIdx.y * BM;
    const int n_base = blockIdx.x * BN;

    // ---- fill: thread t -> row t>>1 (0..255), half t&1 (16 floats -> 8 b32) ----
    {
        const int row  = tid >> 1;
        const int half = tid & 1;
        const int kb0  = half * 8;            // b32 col base
        float nrm = 0.f;

        if (row < BM) {
            const float4* src = (const float4*)(x + (size_t)(m_base + row) * KD);
            unsigned* dst = &As[row * PW + kb0];
            #pragma unroll
            for (int q = 0; q < 4; ++q) {
                float4 v = src[half * 4 + q];
                nrm = fmaf(v.x, v.x, nrm); nrm = fmaf(v.y, v.y, nrm);
                nrm = fmaf(v.z, v.z, nrm); nrm = fmaf(v.w, v.w, nrm);
                dst[2 * q]     = pack_bf16(v.x, v.y);
                dst[2 * q + 1] = pack_bf16(v.z, v.w);
            }
        } else {
            const int brow = row - BM;                 // logical w-row in tile
            const int srow = (brow & ~15) | sig16(brow & 15);   // sigma placement
            const int gn   = n_base + brow;
            unsigned* dst = &Bs[srow * PW + kb0];
            if (gn < N) {
                const float4* src = (const float4*)(w + (size_t)gn * KD);
                #pragma unroll
                for (int q = 0; q < 4; ++q) {
                    float4 v = src[half * 4 + q];
                    nrm = fmaf(v.x, v.x, nrm); nrm = fmaf(v.y, v.y, nrm);
                    nrm = fmaf(v.z, v.z, nrm); nrm = fmaf(v.w, v.w, nrm);
                    dst[2 * q]     = pack_bf16(v.x, v.y);
                    dst[2 * q + 1] = pack_bf16(v.z, v.w);
                }
            } else {
                #pragma unroll
                for (int q = 0; q < 8; ++q) dst[q] = 0u;
            }
        }
        p2[tid] = nrm;
    }
    __syncthreads();

    if (tid < BM) {
        x2s[tid] = p2[2 * tid] + p2[2 * tid + 1];
    } else if (tid < BM + BN) {
        const int r = tid - BM;
        w2s[r] = p2[2 * tid] + p2[2 * tid + 1];   // indexed by LOGICAL col
    }
    __syncthreads();

    // ---- 4x4 warp grid, 32x32 warp tile, 2 k16 steps ----
    const int lane   = tid & 31;
    const int wid    = tid >> 5;
    const int warp_m = (wid & 3) * 32;    // 4 warps along M
    const int warp_n = (wid >> 2) * 32;   // 4 warps along N
    const int qr     = lane >> 2;         // 0..7
    const int qc     = lane & 3;          // 0..3

    // sigma placement turns the permuted fragment-row pattern into plain
    // {qr + (tn&1)*8 + (tn>>1)*16}; acc ownership stays: thread owns logical
    // cols warp_n + qc*4 + i*16 + {0..3} for fragment pair (2i, 2i+1).
    const unsigned* a_base = &As[(warp_m + qr) * PW + qc];
    const unsigned* b_base = &Bs[(warp_n + qr) * PW + qc];

    float acc[2][4][4];
    #pragma unroll
    for (int i = 0; i < 2; ++i)
        #pragma unroll
        for (int j = 0; j < 4; ++j)
            #pragma unroll
            for (int v = 0; v < 4; ++v) acc[i][j][v] = 0.f;

    #pragma unroll
    for (int ks = 0; ks < 2; ++ks) {
        const int o = ks * 8;             // b32 offset of this k16 chunk

        unsigned af[2][4];
        #pragma unroll
        for (int tm = 0; tm < 2; ++tm) {
            const unsigned* r0 = a_base + tm * 16 * PW;
            af[tm][0] = r0[o];                 // row qr,    k 2qc..2qc+1
            af[tm][1] = r0[8 * PW + o];        // row qr+8
            af[tm][2] = r0[o + 4];             // row qr,    k 2qc+8..
            af[tm][3] = r0[8 * PW + o + 4];    // row qr+8
        }

        unsigned bf[4][2];
        #pragma unroll
        for (int tn = 0; tn < 4; ++tn) {
            const unsigned* c0 = b_base + ((tn >> 1) * 16 + (tn & 1) * 8) * PW;
            bf[tn][0] = c0[o];
            bf[tn][1] = c0[o + 4];
        }

        #pragma unroll
        for (int tm = 0; tm < 2; ++tm)
            #pragma unroll
            for (int tn = 0; tn < 4; ++tn)
                mma_bf16(acc[tm][tn], af[tm], bf[tn]);
    }

    // ---- epilogue: thread owns cols warp_n + qc*4 + i*16 + {0..3} ----
    #pragma unroll
    for (int tm = 0; tm < 2; ++tm) {
        const int r_lo = warp_m + tm * 16 + qr;
        const float x2_lo = x2s[r_lo];
        const float x2_hi = x2s[r_lo + 8];
        const size_t off_lo = (size_t)(m_base + r_lo) * N;
        const size_t off_hi = off_lo + (size_t)8 * N;

        #pragma unroll
        for (int i = 0; i < 2; ++i) {
            const int c  = warp_n + qc * 4 + i * 16;
            const int gn = n_base + c;
            if (gn < N) {                          // N%4==0 -> gn+3 valid
                const float4 w2v = *(const float4*)&w2s[c];
                const float* a0 = acc[tm][2 * i];      // cols c, c+1
                const float* a1 = acc[tm][2 * i + 1];  // cols c+2, c+3

                float4 lo, hi;
                lo.x = fsqrt_approx(fmaxf(fmaf(-2.f, a0[0], x2_lo + w2v.x), 0.f));
                lo.y = fsqrt_approx(fmaxf(fmaf(-2.f, a0[1], x2_lo + w2v.y), 0.f));
                lo.z = fsqrt_approx(fmaxf(fmaf(-2.f, a1[0], x2_lo + w2v.z), 0.f));
                lo.w = fsqrt_approx(fmaxf(fmaf(-2.f, a1[1], x2_lo + w2v.w), 0.f));
                hi.x = fsqrt_approx(fmaxf(fmaf(-2.f, a0[2], x2_hi + w2v.x), 0.f));
                hi.y = fsqrt_approx(fmaxf(fmaf(-2.f, a0[3], x2_hi + w2v.y), 0.f));
                hi.z = fsqrt_approx(fmaxf(fmaf(-2.f, a1[2], x2_hi + w2v.z), 0.f));
                hi.w = fsqrt_approx(fmaxf(fmaf(-2.f, a1[3], x2_hi + w2v.w), 0.f));

                __stcs((float4*)(out + off_lo + gn), lo);
                __stcs((float4*)(out + off_hi + gn), hi);
            }
        }
    }
}

extern "C" void kernel_launch(void* const* d_in, const int* in_sizes, int n_in,
                              void* d_out, int out_size) {
    const float* x = (const float*)d_in[0];
    const float* w = (const float*)d_in[1];
    float* out     = (float*)d_out;

    int B = in_sizes[0] / KD;   // 65536
    int N = in_sizes[1] / KD;   // 4900

    dim3 grid((N + BN - 1) / BN, (B + BM - 1) / BM);
    som_mma_kernel<<<grid, 512>>>(x, w, out, B, N);
}

// round 12
// speedup vs baseline: 1.4637x; 1.4637x over previous
#include <cuda_runtime.h>
#include <cstdint>

// Kohonen SOM pairwise L2 distance via tf32 mma.sync.m16n8k8.
//   out[b][n] = sqrt(max(||x_b||^2 + ||w_n||^2 - 2 x_b.w_n, 0))
// x [B=65536,32] f32, w [N=4900,32] f32, out [B,N] f32.
//
// R12 = R10 (128x128 CTA tile, 512 threads, 4x4 warp grid, 32x32 warp tile,
// pitch-36 smem, permuted fragment columns -> STG.128 epilogue) with the
// fill converted to PURE cp.async: norms are precomputed by a tiny prologue
// kernel into device globals, so tile data never passes through registers
// (no LDG-to-RF, no STS, no smem norm reduction, one fewer syncthreads).
// tf32 MMA consumes raw fp32 bits (HW truncation; validated in R5 at 5.7e-5).

#define BM 128
#define BN 128
#define KD 32
#define SP 36     // padded pitch in floats; (36r+c) % 32 == (4r+c) % 32

#define SIDX(row, col) ((row) * SP + (col))

__device__ float g_x2[65536];
__device__ float g_w2[8192];

__device__ __forceinline__ float fsqrt_approx(float a) {
    float r;
    asm("sqrt.approx.f32 %0, %1;" : "=f"(r) : "f"(a));
    return r;
}

__device__ __forceinline__ unsigned smem_u32(const void* p) {
    unsigned a;
    asm("{ .reg .u64 t; cvta.to.shared.u64 t, %1; cvt.u32.u64 %0, t; }"
        : "=r"(a) : "l"(p));
    return a;
}

__device__ __forceinline__ void cp16(unsigned saddr, const void* gaddr) {
    asm volatile("cp.async.cg.shared.global [%0], [%1], 16;"
                 :: "r"(saddr), "l"(gaddr));
}
__device__ __forceinline__ void cp16_pred(unsigned saddr, const void* gaddr, int sz) {
    asm volatile("cp.async.cg.shared.global [%0], [%1], 16, %2;"
                 :: "r"(saddr), "l"(gaddr), "r"(sz));
}

__device__ __forceinline__ void mma_tf32(float* c, const unsigned* a, const unsigned* b) {
    asm volatile(
        "mma.sync.aligned.m16n8k8.row.col.f32.tf32.tf32.f32 "
        "{%0,%1,%2,%3}, {%4,%5,%6,%7}, {%8,%9}, {%0,%1,%2,%3};"
        : "+f"(c[0]), "+f"(c[1]), "+f"(c[2]), "+f"(c[3])
        : "r"(a[0]), "r"(a[1]), "r"(a[2]), "r"(a[3]),
          "r"(b[0]), "r"(b[1]));
}

// ---- prologue: row norms ----
__global__ void norms_kernel(const float* __restrict__ x,
                             const float* __restrict__ w,
                             int B, int N) {
    int i = blockIdx.x * 256 + threadIdx.x;
    if (i < B) {
        const float4* s = (const float4*)(x + (size_t)i * KD);
        float n = 0.f;
        #pragma unroll
        for (int q = 0; q < 8; ++q) {
            float4 v = s[q];
            n = fmaf(v.x, v.x, n); n = fmaf(v.y, v.y, n);
            n = fmaf(v.z, v.z, n); n = fmaf(v.w, v.w, n);
        }
        g_x2[i] = n;
    }
    if (i < N) {
        const float4* s = (const float4*)(w + (size_t)i * KD);
        float n = 0.f;
        #pragma unroll
        for (int q = 0; q < 8; ++q) {
            float4 v = s[q];
            n = fmaf(v.x, v.x, n); n = fmaf(v.y, v.y, n);
            n = fmaf(v.z, v.z, n); n = fmaf(v.w, v.w, n);
        }
        g_w2[i] = n;
    }
}

__global__ __launch_bounds__(512, 2)
void som_mma_kernel(const float* __restrict__ x,
                    const float* __restrict__ w,
                    float* __restrict__ out,
                    int B, int N) {
    __shared__ float As[BM * SP];     // 18 KB, pitch-36 raw f32(x)
    __shared__ float Bs[BN * SP];     // 18 KB, pitch-36 raw f32(w)

    const int tid    = threadIdx.x;
    const int m_base = blockIdx.y * BM;
    const int n_base = blockIdx.x * BN;

    // ---- fill: 2048 float4s via cp.async, 4 per thread, no RF round-trip ----
    {
        const unsigned as_base = smem_u32(As);
        const unsigned bs_base = smem_u32(Bs);
        #pragma unroll
        for (int p = 0; p < 4; ++p) {
            const int idx = tid + p * 512;       // float4 index, 0..2047
            const int row = (idx >> 3) & 127;    // 8 float4 per row
            const int q4  = (idx & 7) << 2;      // col base (floats)
            if (idx < 1024) {
                cp16(as_base + SIDX(row, q4) * 4,
                     x + (size_t)(m_base + row) * KD + q4);
            } else {
                const int gn = n_base + row;
                const int sz = (gn < N) ? 16 : 0;    // 0 -> zero-fill, no read
                cp16_pred(bs_base + SIDX(row, q4) * 4,
                          w + (size_t)gn * KD + q4, sz);
            }
        }
        asm volatile("cp.async.commit_group;");
        asm volatile("cp.async.wait_group 0;");
    }
    __syncthreads();

    // ---- 4x4 warp grid, 32x32 warp tile, permuted B-fragment columns ----
    const int lane   = tid & 31;
    const int wid    = tid >> 5;
    const int warp_m = (wid & 3) * 32;    // 4 warps along M
    const int warp_n = (wid >> 2) * 32;   // 4 warps along N
    const int qr     = lane >> 2;         // 0..7
    const int qc     = lane & 3;          // 0..3

    // permuted physical w-row for fragment tn, col-slot qr
    const int pq = (qr >> 1) * 4 + (qr & 1);

    const float* a_row0 = &As[SIDX(warp_m + qr, qc)];
    const float* b_row0 = &Bs[SIDX(warp_n + pq, qc)];

    float acc[2][4][4];
    #pragma unroll
    for (int i = 0; i < 2; ++i)
        #pragma unroll
        for (int j = 0; j < 4; ++j)
            #pragma unroll
            for (int v = 0; v < 4; ++v) acc[i][j][v] = 0.f;

    #pragma unroll
    for (int ks = 0; ks < 4; ++ks) {
        const int k0 = ks * 8;

        unsigned af[2][4];
        #pragma unroll
        for (int tm = 0; tm < 2; ++tm) {
            const float* r0 = a_row0 + tm * 16 * SP;
            af[tm][0] = __float_as_uint(r0[k0]);
            af[tm][1] = __float_as_uint(r0[8 * SP + k0]);
            af[tm][2] = __float_as_uint(r0[k0 + 4]);
            af[tm][3] = __float_as_uint(r0[8 * SP + k0 + 4]);
        }

        unsigned bf[4][2];
        #pragma unroll
        for (int tn = 0; tn < 4; ++tn) {
            const float* c0 = b_row0 + ((tn >> 1) * 16 + (tn & 1) * 2) * SP;
            bf[tn][0] = __float_as_uint(c0[k0]);
            bf[tn][1] = __float_as_uint(c0[k0 + 4]);
        }

        #pragma unroll
        for (int tm = 0; tm < 2; ++tm)
            #pragma unroll
            for (int tn = 0; tn < 4; ++tn)
                mma_tf32(acc[tm][tn], af[tm], bf[tn]);
    }

    // ---- epilogue: norms from L2-hot globals; STG.128 per 4-col group ----
    #pragma unroll
    for (int tm = 0; tm < 2; ++tm) {
        const int r_lo = warp_m + tm * 16 + qr;
        const float x2_lo = __ldg(&g_x2[m_base + r_lo]);
        const float x2_hi = __ldg(&g_x2[m_base + r_lo + 8]);
        const size_t off_lo = (size_t)(m_base + r_lo) * N;
        const size_t off_hi = off_lo + (size_t)8 * N;

        #pragma unroll
        for (int i = 0; i < 2; ++i) {
            const int c  = warp_n + qc * 4 + i * 16;
            const int gn = n_base + c;
            if (gn < N) {                          // N%4==0 -> gn+3 valid
                const float4 w2v = __ldg((const float4*)&g_w2[gn]);
                const float* a0 = acc[tm][2 * i];      // cols gn, gn+1
                const float* a1 = acc[tm][2 * i + 1];  // cols gn+2, gn+3

                float4 lo, hi;
                lo.x = fsqrt_approx(fmaxf(fmaf(-2.f, a0[0], x2_lo + w2v.x), 0.f));
                lo.y = fsqrt_approx(fmaxf(fmaf(-2.f, a0[1], x2_lo + w2v.y), 0.f));
                lo.z = fsqrt_approx(fmaxf(fmaf(-2.f, a1[0], x2_lo + w2v.z), 0.f));
                lo.w = fsqrt_approx(fmaxf(fmaf(-2.f, a1[1], x2_lo + w2v.w), 0.f));
                hi.x = fsqrt_approx(fmaxf(fmaf(-2.f, a0[2], x2_hi + w2v.x), 0.f));
                hi.y = fsqrt_approx(fmaxf(fmaf(-2.f, a0[3], x2_hi + w2v.y), 0.f));
                hi.z = fsqrt_approx(fmaxf(fmaf(-2.f, a1[2], x2_hi + w2v.z), 0.f));
                hi.w = fsqrt_approx(fmaxf(fmaf(-2.f, a1[3], x2_hi + w2v.w), 0.f));

                __stcs((float4*)(out + off_lo + gn), lo);
                __stcs((float4*)(out + off_hi + gn), hi);
            }
        }
    }
}

extern "C" void kernel_launch(void* const* d_in, const int* in_sizes, int n_in,
                              void* d_out, int out_size) {
    const float* x = (const float*)d_in[0];
    const float* w = (const float*)d_in[1];
    float* out     = (float*)d_out;

    int B = in_sizes[0] / KD;   // 65536
    int N = in_sizes[1] / KD;   // 4900

    norms_kernel<<<(B + 255) / 256, 256>>>(x, w, B, N);

    dim3 grid((N + BN - 1) / BN, (B + BM - 1) / BM);
    som_mma_kernel<<<grid, 512>>>(x, w, out, B, N);
}